// round 16
// baseline (speedup 1.0000x reference)
#include <cuda_runtime.h>
#include <cuda_bf16.h>
#include <cuda_fp16.h>
#include <cstdint>

#define B_  16
#define N_  1024
#define S_  256
#define D_  1024
#define HQ  16
#define HKV 8
#define HD  64
#define KVE 512

// ---------------- scratch (device globals; no cudaMalloc allowed) ----------
__device__ __half g_xq [(size_t)B_*N_*D_];
__device__ __half g_yq [(size_t)B_*S_*D_];
__device__ __half g_a2q[(size_t)B_*N_*D_];
__device__ __half g_wqt[D_*D_];
__device__ __half g_wkt[KVE*D_];
__device__ __half g_wvt[KVE*D_];
__device__ __half g_wot[D_*D_];
__device__ __half g_qh[(size_t)B_*N_*D_];
__device__ __half g_ql[(size_t)B_*N_*D_];
__device__ __half g_kh[(size_t)B_*S_*KVE];
__device__ __half g_kl[(size_t)B_*S_*KVE];
__device__ __half g_vh[(size_t)B_*S_*KVE];
__device__ __half g_vl[(size_t)B_*S_*KVE];
__device__ float  g_att[(size_t)B_*N_*D_];
__device__ float  g_rfx[B_*N_];
__device__ float  g_rfy[B_*S_];
__device__ float  g_rf2[B_*N_];
__device__ double g_part[4*256];
__device__ double g_wsum[4];

#define LO_SCALE   1024.0f
#define LO_INV     (1.0f/1024.0f)

// ---------------- warp reductions -------------------------------------------
__device__ __forceinline__ void warp_sum2(float& a, float& b) {
    #pragma unroll
    for (int o = 16; o; o >>= 1) {
        a += __shfl_xor_sync(0xffffffffu, a, o);
        b += __shfl_xor_sync(0xffffffffu, b, o);
    }
}
__device__ __forceinline__ void warp_summax(float& s, float& m) {
    #pragma unroll
    for (int o = 16; o; o >>= 1) {
        s += __shfl_xor_sync(0xffffffffu, s, o);
        m = fmaxf(m, __shfl_xor_sync(0xffffffffu, m, o));
    }
}
__device__ __forceinline__ float block_sum(float v, float* sbuf) {
    #pragma unroll
    for (int o = 16; o; o >>= 1) v += __shfl_xor_sync(0xffffffffu, v, o);
    int w = threadIdx.x >> 5, l = threadIdx.x & 31;
    if (!l) sbuf[w] = v;
    __syncthreads();
    if (threadIdx.x < 8) {
        v = sbuf[threadIdx.x];
        #pragma unroll
        for (int o = 4; o; o >>= 1) v += __shfl_xor_sync(0x000000ffu, v, o);
        if (!threadIdx.x) sbuf[0] = v;
    }
    __syncthreads();
    v = sbuf[0];
    __syncthreads();
    return v;
}

// ---------------- fused act_quant + absmean ---------------------------------
__device__ __forceinline__ uint32_t q2h(float a, float b, float r, float sc) {
    __half qa = __float2half_rn(fminf(fmaxf(rintf((a*r)*sc), -128.f), 127.f));
    __half qb = __float2half_rn(fminf(fmaxf(rintf((b*r)*sc), -128.f), 127.f));
    return ((uint32_t)__half_as_ushort(qb) << 16) | __half_as_ushort(qa);
}

// y==0: act_quant rows; y==1: absmean partial sums
__global__ void __launch_bounds__(256) prep_kernel(const float* __restrict__ X,
                                                   const float* __restrict__ Y,
                                                   const float* __restrict__ w0,
                                                   const float* __restrict__ w1,
                                                   const float* __restrict__ w2,
                                                   const float* __restrict__ w3) {
    if (blockIdx.y == 1) {
        __shared__ float sbuf[16];
        int slot = blockIdx.x >> 8;
        int bx   = blockIdx.x & 255;
        const float* w = slot == 0 ? w0 : slot == 1 ? w1 : slot == 2 ? w2 : w3;
        int n4 = ((slot == 1 || slot == 2) ? KVE * D_ : D_ * D_) >> 2;
        const float4* w4 = (const float4*)w;
        float s = 0.f;
        for (int i = bx * 256 + threadIdx.x; i < n4; i += 256 * 256) {
            float4 v = w4[i];
            s += fabsf(v.x) + fabsf(v.y) + fabsf(v.z) + fabsf(v.w);
        }
        s = block_sum(s, sbuf);
        if (!threadIdx.x) g_part[slot * 256 + bx] = (double)s;
        return;
    }
    int rid  = blockIdx.x * 8 + (threadIdx.x >> 5);
    int lane = threadIdx.x & 31;
    if (rid >= B_ * N_ + B_ * S_) return;
    int which = rid >= B_ * N_;
    size_t row = which ? rid - B_ * N_ : rid;
    const float* src = (which ? Y : X) + row * D_;
    __half* Q   = (which ? g_yq : g_xq) + row * D_;
    float*  RF  = which ? g_rfy : g_rfx;

    float4 v[8];
    #pragma unroll
    for (int j = 0; j < 8; j++) v[j] = ((const float4*)src)[lane + j * 32];

    float ssq = 0.f, am = 0.f;
    #pragma unroll
    for (int j = 0; j < 8; j++) {
        ssq += v[j].x*v[j].x + v[j].y*v[j].y + v[j].z*v[j].z + v[j].w*v[j].w;
        am = fmaxf(am, fmaxf(fmaxf(fabsf(v[j].x), fabsf(v[j].y)),
                             fmaxf(fabsf(v[j].z), fabsf(v[j].w))));
    }
    warp_summax(ssq, am);
    float r = 1.0f / sqrtf(ssq * (1.0f/1024.0f) + 1e-6f);
    am *= r;
    float sc = 127.0f / fmaxf(am, 1e-5f);

    #pragma unroll
    for (int j = 0; j < 8; j++) {
        uint2 st;
        st.x = q2h(v[j].x, v[j].y, r, sc);
        st.y = q2h(v[j].z, v[j].w, r, sc);
        *(uint2*)(Q + (lane + j * 32) * 4) = st;
    }
    if (!lane) RF[row] = 1.0f / sc;
}

__global__ void __launch_bounds__(256) reduce_kernel() {
    __shared__ double sd[256];
    int slot = blockIdx.x;
    sd[threadIdx.x] = g_part[slot * 256 + threadIdx.x];
    __syncthreads();
    for (int o = 128; o; o >>= 1) {
        if (threadIdx.x < o) sd[threadIdx.x] += sd[threadIdx.x + o];
        __syncthreads();
    }
    if (!threadIdx.x) g_wsum[slot] = sd[0];
}
__global__ void __launch_bounds__(256) wquant_all_kernel(const float* __restrict__ w0,
    const float* __restrict__ w1, const float* __restrict__ w2, const float* __restrict__ w3) {
    int slot = blockIdx.y;
    const float* w = slot == 0 ? w0 : slot == 1 ? w1 : slot == 2 ? w2 : w3;
    __half* out = slot == 0 ? g_wqt : slot == 1 ? g_wkt : slot == 2 ? g_wvt : g_wot;
    int n = (slot == 1 || slot == 2) ? KVE * D_ : D_ * D_;
    int n4 = n >> 2;
    double invcnt = 1.0 / (double)n;
    float mean  = (float)(g_wsum[slot] * invcnt);
    float scale = 1.0f / fmaxf(mean, 1e-5f);
    const float4* w4 = (const float4*)w;
    for (int i = blockIdx.x * 256 + threadIdx.x; i < n4; i += gridDim.x * 256) {
        float4 v = w4[i];
        float t0 = fminf(fmaxf(rintf(v.x * scale), -1.f), 1.f);
        float t1 = fminf(fmaxf(rintf(v.y * scale), -1.f), 1.f);
        float t2 = fminf(fmaxf(rintf(v.z * scale), -1.f), 1.f);
        float t3 = fminf(fmaxf(rintf(v.w * scale), -1.f), 1.f);
        uint2 st;
        st.x = ((uint32_t)__half_as_ushort(__float2half_rn(t1)) << 16)
             | __half_as_ushort(__float2half_rn(t0));
        st.y = ((uint32_t)__half_as_ushort(__float2half_rn(t3)) << 16)
             | __half_as_ushort(__float2half_rn(t2));
        *(uint2*)(out + i * 4) = st;
    }
}

// ---------------- fused LayerNorm + rms_norm + act_quant (warp-per-row) ----
__global__ void __launch_bounds__(256) ln_quant_kernel(const float* __restrict__ gamma,
                                                       const float* __restrict__ beta) {
    int rid  = blockIdx.x * 8 + (threadIdx.x >> 5);
    int lane = threadIdx.x & 31;
    const float* src = g_att + (size_t)rid * D_;

    float4 v[8], gv[8], bv[8];
    #pragma unroll
    for (int j = 0; j < 8; j++) {
        v[j]  = ((const float4*)src)[lane + j * 32];
        gv[j] = ((const float4*)gamma)[lane + j * 32];
        bv[j] = ((const float4*)beta)[lane + j * 32];
    }

    float s = 0.f, sq = 0.f;
    #pragma unroll
    for (int j = 0; j < 8; j++) {
        s  += v[j].x + v[j].y + v[j].z + v[j].w;
        sq += v[j].x*v[j].x + v[j].y*v[j].y + v[j].z*v[j].z + v[j].w*v[j].w;
    }
    warp_sum2(s, sq);
    float mu  = s * (1.0f/1024.0f);
    float var = sq * (1.0f/1024.0f) - mu * mu;
    float rs  = 1.0f / sqrtf(var + 1e-5f);

    float m2 = 0.f, am = 0.f;
    #pragma unroll
    for (int j = 0; j < 8; j++) {
        v[j].x = ((v[j].x - mu) * rs) * gv[j].x + bv[j].x;
        v[j].y = ((v[j].y - mu) * rs) * gv[j].y + bv[j].y;
        v[j].z = ((v[j].z - mu) * rs) * gv[j].z + bv[j].z;
        v[j].w = ((v[j].w - mu) * rs) * gv[j].w + bv[j].w;
        m2 += v[j].x*v[j].x + v[j].y*v[j].y + v[j].z*v[j].z + v[j].w*v[j].w;
        am = fmaxf(am, fmaxf(fmaxf(fabsf(v[j].x), fabsf(v[j].y)),
                             fmaxf(fabsf(v[j].z), fabsf(v[j].w))));
    }
    warp_summax(m2, am);
    float r2 = 1.0f / sqrtf(m2 * (1.0f/1024.0f) + 1e-6f);
    am *= r2;
    float sc = 127.0f / fmaxf(am, 1e-5f);

    __half* Q = g_a2q + (size_t)rid * D_;
    #pragma unroll
    for (int j = 0; j < 8; j++) {
        uint2 st;
        st.x = q2h(v[j].x, v[j].y, r2, sc);
        st.y = q2h(v[j].z, v[j].w, r2, sc);
        *(uint2*)(Q + (lane + j * 32) * 4) = st;
    }
    if (!lane) g_rf2[rid] = 1.0f / sc;
}

// ---------------- mma / ldmatrix / cp.async helpers -------------------------
__device__ __forceinline__ void ldsm4(uint32_t (&r)[4], uint32_t a) {
    asm volatile("ldmatrix.sync.aligned.m8n8.x4.shared.b16 {%0,%1,%2,%3}, [%4];"
                 : "=r"(r[0]), "=r"(r[1]), "=r"(r[2]), "=r"(r[3]) : "r"(a));
}
__device__ __forceinline__ void ldsm4t(uint32_t (&r)[4], uint32_t a) {
    asm volatile("ldmatrix.sync.aligned.m8n8.x4.trans.shared.b16 {%0,%1,%2,%3}, [%4];"
                 : "=r"(r[0]), "=r"(r[1]), "=r"(r[2]), "=r"(r[3]) : "r"(a));
}
__device__ __forceinline__ void mma_f16(float (&d)[4], const uint32_t (&a)[4],
                                        uint32_t b0, uint32_t b1) {
    asm volatile("mma.sync.aligned.m16n8k16.row.col.f32.f16.f16.f32 "
                 "{%0,%1,%2,%3}, {%4,%5,%6,%7}, {%8,%9}, {%0,%1,%2,%3};"
                 : "+f"(d[0]), "+f"(d[1]), "+f"(d[2]), "+f"(d[3])
                 : "r"(a[0]), "r"(a[1]), "r"(a[2]), "r"(a[3]), "r"(b0), "r"(b1));
}
__device__ __forceinline__ void mma_f16a(uint32_t (&d)[2], const uint32_t (&a)[4],
                                         uint32_t b0, uint32_t b1) {
    asm volatile("mma.sync.aligned.m16n8k16.row.col.f16.f16.f16.f16 "
                 "{%0,%1}, {%2,%3,%4,%5}, {%6,%7}, {%0,%1};"
                 : "+r"(d[0]), "+r"(d[1])
                 : "r"(a[0]), "r"(a[1]), "r"(a[2]), "r"(a[3]), "r"(b0), "r"(b1));
}
__device__ __forceinline__ void cpa16(uint32_t s, const void* g) {
    asm volatile("cp.async.cg.shared.global [%0], [%1], 16;" :: "r"(s), "l"(g));
}
#define CP_COMMIT asm volatile("cp.async.commit_group;")
#define CP_WAIT1  asm volatile("cp.async.wait_group 1;")
#define CP_WAIT0  asm volatile("cp.async.wait_group 0;")

__device__ __forceinline__ uint32_t pack_hl16(float x, float y, uint32_t& lo) {
    __half hx = __float2half_rn(x), hy = __float2half_rn(y);
    __half lx = __float2half_rn((x - __half2float(hx)) * LO_SCALE);
    __half ly = __float2half_rn((y - __half2float(hy)) * LO_SCALE);
    lo = ((uint32_t)__half_as_ushort(ly) << 16) | __half_as_ushort(lx);
    return ((uint32_t)__half_as_ushort(hy) << 16) | __half_as_ushort(hx);
}
__device__ __forceinline__ float2 unp16(uint32_t u) {
    __half2 h = *(__half2*)&u;
    return __half22float2(h);
}

// ---------------- exact integer GEMM via fp16 MMA ---------------------------
// 128x128 tile, k-chunk 64, 3-stage cp.async. Stage = 2 * 128 rows x 72 fp16
// = 36864 B. 3 stages = 110592 B; 2 CTAs/SM fit in 228 KB.
#define G_STG   36864u
#define G_SMEM3 (3 * 36864)
template<int MODE>   // 0: fp32 C; 1: hi/lo fp16 planes
__device__ __forceinline__ void gemm3(const __half* __restrict__ A,
                                      const __half* __restrict__ W,
                                      float* __restrict__ C,
                                      __half* __restrict__ Ch,
                                      __half* __restrict__ Cl,
                                      const float* __restrict__ rowf,
                                      int slot, double invcnt, float extra, int Nn,
                                      int m0, int n0) {
    extern __shared__ char smg[];
    const int K = 1024, T = 16;            // 16 chunks of 64
    int tid = threadIdx.x, lane = tid & 31, w = tid >> 5;
    int warpM = w & 1, warpN = w >> 1;
    int m0_ = m0, n0_ = n0;

    float acc[4][4][4];
    #pragma unroll
    for (int a = 0; a < 4; a++)
        #pragma unroll
        for (int b = 0; b < 4; b++)
            #pragma unroll
            for (int c = 0; c < 4; c++) acc[a][b][c] = 0.f;

    uint32_t sAb = (uint32_t)__cvta_generic_to_shared(smg);
    uint32_t sBb = sAb + 128 * 72 * 2;     // B follows A in each stage
    int aRow = warpM * 64 + (lane & 15);
    int aCol = (lane >> 4) << 3;
    int bRow = warpN * 32 + ((lane & 16) >> 1) + (lane & 7);
    int bCol = lane & 8;
    // loader: 128 B/row = 8 chunks of 16B; 128 rows x 8 = 1024 chunks/matrix;
    // 256 threads -> 4 chunks per thread per matrix.
    int ldr = tid >> 1, ldc = (tid & 1) * 16;

    #define GLOAD(t, buf) do {                                                 \
        uint32_t bo = (uint32_t)(buf) * G_STG;                                 \
        int k0 = (t) * 64;                                                     \
        _Pragma("unroll")                                                      \
        for (int i = 0; i < 4; i++) {                                          \
            int cc = ldc + i * 32;                                             \
            cpa16(sAb + bo + (uint32_t)(ldr * 144 + cc),                       \
                  A + (size_t)(m0_ + ldr) * K + k0 + cc / 2);                  \
            cpa16(sBb + bo + (uint32_t)(ldr * 144 + cc),                       \
                  W + (size_t)(n0_ + ldr) * K + k0 + cc / 2);                  \
        }                                                                      \
    } while (0)

    GLOAD(0, 0); CP_COMMIT;
    GLOAD(1, 1); CP_COMMIT;

    #pragma unroll 1
    for (int t = 0; t < T; t++) {
        if (t + 1 < T) { CP_WAIT1; } else { CP_WAIT0; }
        __syncthreads();
        if (t + 2 < T) GLOAD(t + 2, (t + 2) % 3);
        CP_COMMIT;
        uint32_t bo = (uint32_t)(t % 3) * G_STG;
        #pragma unroll
        for (int ks = 0; ks < 64; ks += 16) {
            uint32_t af[4][4];
            #pragma unroll
            for (int mi = 0; mi < 4; mi++)
                ldsm4(af[mi], sAb + bo + (uint32_t)(((aRow + mi * 16) * 72 + ks + aCol) * 2));
            uint32_t bf[2][4];
            #pragma unroll
            for (int nb = 0; nb < 2; nb++)
                ldsm4(bf[nb], sBb + bo + (uint32_t)(((bRow + nb * 16) * 72 + ks + bCol) * 2));
            #pragma unroll
            for (int mi = 0; mi < 4; mi++)
                #pragma unroll
                for (int ni = 0; ni < 4; ni++)
                    mma_f16(acc[mi][ni], af[mi],
                            bf[ni >> 1][(ni & 1) * 2], bf[ni >> 1][(ni & 1) * 2 + 1]);
        }
        // no trailing barrier: buf t%3 is rewritten by GLOAD(t+3) at iter t+1,
        // which is after iter t+1's top __syncthreads -> all warps done reading.
    }
    #undef GLOAD

    float wf = fmaxf((float)(g_wsum[slot] * invcnt), 1e-5f);
    float sgl = wf * extra;
    #pragma unroll
    for (int mi = 0; mi < 4; mi++) {
        int m = m0_ + warpM * 64 + mi * 16 + (lane >> 2);
        float f0 = rowf[m] * sgl, f1 = rowf[m + 8] * sgl;
        #pragma unroll
        for (int ni = 0; ni < 4; ni++) {
            int n = n0_ + warpN * 32 + ni * 8 + (lane & 3) * 2;
            if (MODE == 0) {
                *(float2*)(C + (size_t)m * Nn + n) =
                    make_float2(acc[mi][ni][0] * f0, acc[mi][ni][1] * f0);
                *(float2*)(C + (size_t)(m + 8) * Nn + n) =
                    make_float2(acc[mi][ni][2] * f1, acc[mi][ni][3] * f1);
            } else {
                uint32_t lo0, lo1;
                uint32_t hi0 = pack_hl16(acc[mi][ni][0] * f0, acc[mi][ni][1] * f0, lo0);
                uint32_t hi1 = pack_hl16(acc[mi][ni][2] * f1, acc[mi][ni][3] * f1, lo1);
                *(uint32_t*)(Ch + (size_t)m * Nn + n) = hi0;
                *(uint32_t*)(Cl + (size_t)m * Nn + n) = lo0;
                *(uint32_t*)(Ch + (size_t)(m + 8) * Nn + n) = hi1;
                *(uint32_t*)(Cl + (size_t)(m + 8) * Nn + n) = lo1;
            }
        }
    }
}

// merged q/k/v projection GEMM: blocks [0,1024) = q, [1024,1152) = k, [1152,1280) = v
__global__ void __launch_bounds__(256, 2) gemm_qkv_kernel() {
    int blk = blockIdx.x;
    if (blk < 1024) {
        gemm3<1>(g_xq, g_wqt, nullptr, g_qh, g_ql, g_rfx, 0, 1.0/(1024.0*1024.0),
                 0.125f, D_, (blk >> 3) * 128, (blk & 7) * 128);
    } else if (blk < 1152) {
        int t = blk - 1024;
        gemm3<1>(g_yq, g_wkt, nullptr, g_kh, g_kl, g_rfy, 1, 1.0/(512.0*1024.0),
                 1.0f, KVE, (t >> 2) * 128, (t & 3) * 128);
    } else {
        int t = blk - 1152;
        gemm3<1>(g_yq, g_wvt, nullptr, g_vh, g_vl, g_rfy, 2, 1.0/(512.0*1024.0),
                 1.0f, KVE, (t >> 2) * 128, (t & 3) * 128);
    }
}
__global__ void __launch_bounds__(256, 2) gemm_o_kernel(float* __restrict__ out) {
    gemm3<0>(g_a2q, g_wot, out, nullptr, nullptr, g_rf2, 3, 1.0/(1024.0*1024.0),
             1.0f, D_, (int)blockIdx.y * 128, (int)blockIdx.x * 128);
}

// ---------------- attention: fp16 hi/lo, cross terms in f16-acc MMA --------
#define ATT_SMEM ((2 * 256 * 72 + 2 * 64 * 72) * 2)

__global__ void __launch_bounds__(128, 2) attn_mma_kernel() {
    extern __shared__ __half smh[];
    __half* sKVh = smh;
    __half* sKVl = smh + 256 * 72;
    __half* sQh  = smh + 2 * 256 * 72;
    __half* sQl  = sQh + 64 * 72;

    int tid = threadIdx.x, lane = tid & 31, w = tid >> 5;
    int blk = blockIdx.x;
    int qt = blk & 15, qh = (blk >> 4) & 15, b = blk >> 8;
    int h = qh >> 1;

    uint32_t sQhB  = (uint32_t)__cvta_generic_to_shared(sQh);
    uint32_t sQlB  = (uint32_t)__cvta_generic_to_shared(sQl);
    uint32_t sKVhB = (uint32_t)__cvta_generic_to_shared(sKVh);
    uint32_t sKVlB = (uint32_t)__cvta_generic_to_shared(sKVl);

    const __half* Qh = g_qh + ((size_t)(b * N_ + qt * 64)) * D_ + qh * HD;
    const __half* Ql = g_ql + ((size_t)(b * N_ + qt * 64)) * D_ + qh * HD;
    const __half* Kh = g_kh + (size_t)b * S_ * KVE + h * HD;
    const __half* Kl = g_kl + (size_t)b * S_ * KVE + h * HD;
    const __half* Vh = g_vh + (size_t)b * S_ * KVE + h * HD;
    const __half* Vl = g_vl + (size_t)b * S_ * KVE + h * HD;

    #pragma unroll
    for (int i = tid; i < 512; i += 128) {
        int r = i >> 3, c = (i & 7) * 16;
        cpa16(sQhB + (uint32_t)(r * 144 + c), Qh + (size_t)r * D_ + c / 2);
        cpa16(sQlB + (uint32_t)(r * 144 + c), Ql + (size_t)r * D_ + c / 2);
    }
    CP_COMMIT;
    #pragma unroll
    for (int i = tid; i < 2048; i += 128) {
        int r = i >> 3, c = (i & 7) * 16;
        cpa16(sKVhB + (uint32_t)(r * 144 + c), Kh + (size_t)r * KVE + c / 2);
        cpa16(sKVlB + (uint32_t)(r * 144 + c), Kl + (size_t)r * KVE + c / 2);
    }
    CP_COMMIT;

    CP_WAIT1;
    __syncthreads();

    int arow = w * 16 + (lane & 15);
    int acb  = (lane & 16) >> 1;
    uint32_t qhf[4][4], qlf[4][4];
    #pragma unroll
    for (int kt = 0; kt < 4; kt++) {
        uint32_t off = (uint32_t)((arow * 72 + kt * 16 + acb) * 2);
        ldsm4(qhf[kt], sQhB + off);
        ldsm4(qlf[kt], sQlB + off);
    }

    CP_WAIT0;
    __syncthreads();

    float c[32][4];
    #pragma unroll
    for (int i = 0; i < 32; i++)
        #pragma unroll
        for (int j = 0; j < 4; j++) c[i][j] = 0.f;

    int brow = (lane & 7) + ((lane & 16) >> 1);
    int bcol = lane & 8;
    #pragma unroll
    for (int np = 0; np < 16; np++) {
        uint32_t cc0[2] = {0u, 0u}, cc1[2] = {0u, 0u};
        #pragma unroll
        for (int kt = 0; kt < 4; kt++) {
            uint32_t off = (uint32_t)(((np * 16 + brow) * 72 + kt * 16 + bcol) * 2);
            uint32_t bh[4], bl[4];
            ldsm4(bh, sKVhB + off);
            ldsm4(bl, sKVlB + off);
            mma_f16(c[2*np  ], qhf[kt], bh[0], bh[1]);
            mma_f16(c[2*np+1], qhf[kt], bh[2], bh[3]);
            mma_f16a(cc0, qhf[kt], bl[0], bl[1]);
            mma_f16a(cc0, qlf[kt], bh[0], bh[1]);
            mma_f16a(cc1, qhf[kt], bl[2], bl[3]);
            mma_f16a(cc1, qlf[kt], bh[2], bh[3]);
        }
        float2 u0 = unp16(cc0[0]), u1 = unp16(cc0[1]);
        float2 u2 = unp16(cc1[0]), u3 = unp16(cc1[1]);
        c[2*np  ][0] += u0.x * LO_INV; c[2*np  ][1] += u0.y * LO_INV;
        c[2*np  ][2] += u1.x * LO_INV; c[2*np  ][3] += u1.y * LO_INV;
        c[2*np+1][0] += u2.x * LO_INV; c[2*np+1][1] += u2.y * LO_INV;
        c[2*np+1][2] += u3.x * LO_INV; c[2*np+1][3] += u3.y * LO_INV;
    }
    __syncthreads();

    #pragma unroll
    for (int i = tid; i < 2048; i += 128) {
        int r = i >> 3, cc = (i & 7) * 16;
        cpa16(sKVhB + (uint32_t)(r * 144 + cc), Vh + (size_t)r * KVE + cc / 2);
        cpa16(sKVlB + (uint32_t)(r * 144 + cc), Vl + (size_t)r * KVE + cc / 2);
    }
    CP_COMMIT;

    float mx0 = -1e30f, mx1 = -1e30f;
    #pragma unroll
    for (int nt = 0; nt < 32; nt++) {
        mx0 = fmaxf(mx0, fmaxf(c[nt][0], c[nt][1]));
        mx1 = fmaxf(mx1, fmaxf(c[nt][2], c[nt][3]));
    }
    mx0 = fmaxf(mx0, __shfl_xor_sync(0xffffffffu, mx0, 1));
    mx0 = fmaxf(mx0, __shfl_xor_sync(0xffffffffu, mx0, 2));
    mx1 = fmaxf(mx1, __shfl_xor_sync(0xffffffffu, mx1, 1));
    mx1 = fmaxf(mx1, __shfl_xor_sync(0xffffffffu, mx1, 2));
    float s0 = 0.f, s1 = 0.f;
    #pragma unroll
    for (int nt = 0; nt < 32; nt++) {
        c[nt][0] = __expf(c[nt][0] - mx0); s0 += c[nt][0];
        c[nt][1] = __expf(c[nt][1] - mx0); s0 += c[nt][1];
        c[nt][2] = __expf(c[nt][2] - mx1); s1 += c[nt][2];
        c[nt][3] = __expf(c[nt][3] - mx1); s1 += c[nt][3];
    }
    s0 += __shfl_xor_sync(0xffffffffu, s0, 1);
    s0 += __shfl_xor_sync(0xffffffffu, s0, 2);
    s1 += __shfl_xor_sync(0xffffffffu, s1, 1);
    s1 += __shfl_xor_sync(0xffffffffu, s1, 2);
    float i0 = 1.0f / s0, i1 = 1.0f / s1;
    #pragma unroll
    for (int nt = 0; nt < 32; nt++) {
        c[nt][0] *= i0; c[nt][1] *= i0; c[nt][2] *= i1; c[nt][3] *= i1;
    }
    CP_WAIT0;
    __syncthreads();

    float o[8][4];
    uint32_t oc[8][2];
    #pragma unroll
    for (int i = 0; i < 8; i++) {
        oc[i][0] = 0u; oc[i][1] = 0u;
        #pragma unroll
        for (int j = 0; j < 4; j++) o[i][j] = 0.f;
    }

    int vrow = (lane & 7) + (lane & 8);
    int vcb  = (lane & 16) >> 1;
    #pragma unroll
    for (int kt = 0; kt < 16; kt++) {
        uint32_t phi[4], plo[4];
        phi[0] = pack_hl16(c[2*kt  ][0], c[2*kt  ][1], plo[0]);
        phi[1] = pack_hl16(c[2*kt  ][2], c[2*kt  ][3], plo[1]);
        phi[2] = pack_hl16(c[2*kt+1][0], c[2*kt+1][1], plo[2]);
        phi[3] = pack_hl16(c[2*kt+1][2], c[2*kt+1][3], plo[3]);
        #pragma unroll
        for (int dp = 0; dp < 4; dp++) {
            uint32_t off = (uint32_t)(((kt * 16 + vrow) * 72 + dp * 16 + vcb) * 2);
            uint32_t bh[4], bl[4];
            ldsm4t(bh, sKVhB + off);
            ldsm4t(bl, sKVlB + off);
            mma_f16(o[2*dp  ], phi, bh[0], bh[1]);
            mma_f16(o[2*dp+1], phi, bh[2], bh[3]);
            mma_f16a(oc[2*dp  ], phi, bl[0], bl[1]);
            mma_f16a(oc[2*dp  ], plo, bh[0], bh[1]);
            mma_f16a(oc[2*dp+1], phi, bl[2], bl[3]);
            mma_f16a(oc[2*dp+1], plo, bh[2], bh[3]);
        }
    }
    #pragma unroll
    for (int i = 0; i < 8; i++) {
        float2 u0 = unp16(oc[i][0]), u1 = unp16(oc[i][1]);
        o[i][0] += u0.x * LO_INV; o[i][1] += u0.y * LO_INV;
        o[i][2] += u1.x * LO_INV; o[i][3] += u1.y * LO_INV;
    }

    float* Ob = g_att + ((size_t)(b * N_ + qt * 64 + w * 16 + (lane >> 2))) * D_ + qh * HD;
    #pragma unroll
    for (int nt = 0; nt < 8; nt++) {
        int col = nt * 8 + (lane & 3) * 2;
        *(float2*)(Ob + col)          = make_float2(o[nt][0], o[nt][1]);
        *(float2*)(Ob + 8 * D_ + col) = make_float2(o[nt][2], o[nt][3]);
    }
}

// ---------------- launch ----------------------------------------------------
extern "C" void kernel_launch(void* const* d_in, const int* in_sizes, int n_in,
                              void* d_out, int out_size) {
    const float* x  = (const float*)d_in[0];
    const float* y  = (const float*)d_in[1];
    const float* wq = (const float*)d_in[2];
    const float* wk = (const float*)d_in[3];
    const float* wv = (const float*)d_in[4];
    const float* wo = (const float*)d_in[5];
    const float* gamma = (const float*)d_in[6];
    const float* beta  = (const float*)d_in[7];
    float* out = (float*)d_out;

    cudaFuncSetAttribute(attn_mma_kernel,
                         cudaFuncAttributeMaxDynamicSharedMemorySize, ATT_SMEM);
    cudaFuncSetAttribute(gemm_qkv_kernel, cudaFuncAttributeMaxDynamicSharedMemorySize, G_SMEM3);
    cudaFuncSetAttribute(gemm_o_kernel,   cudaFuncAttributeMaxDynamicSharedMemorySize, G_SMEM3);

    prep_kernel<<<dim3(2560, 2), 256>>>(x, y, wq, wk, wv, wo);
    reduce_kernel<<<4, 256>>>();
    wquant_all_kernel<<<dim3(256, 4), 256>>>(wq, wk, wv, wo);

    gemm_qkv_kernel<<<1280, 256, G_SMEM3>>>();

    attn_mma_kernel<<<B_ * HQ * (N_ / 64), 128, ATT_SMEM>>>();

    ln_quant_kernel<<<B_ * N_ / 8, 256>>>(gamma, beta);
    gemm_o_kernel<<<dim3(8, 128), 256, G_SMEM3>>>(out);
}

// round 17
// speedup vs baseline: 1.1412x; 1.1412x over previous
#include <cuda_runtime.h>
#include <cuda_bf16.h>
#include <cstdint>

#define B_  16
#define N_  1024
#define S_  256
#define D_  1024
#define HQ  16
#define HKV 8
#define HD  64
#define KVE 512

// ---------------- scratch (device globals; no cudaMalloc allowed) ----------
__device__ __nv_bfloat16 g_xq [(size_t)B_*N_*D_];
__device__ __nv_bfloat16 g_yq [(size_t)B_*S_*D_];
__device__ __nv_bfloat16 g_a2q[(size_t)B_*N_*D_];
__device__ __nv_bfloat16 g_wqt[D_*D_];
__device__ __nv_bfloat16 g_wkt[KVE*D_];
__device__ __nv_bfloat16 g_wvt[KVE*D_];
__device__ __nv_bfloat16 g_wot[D_*D_];
__device__ __nv_bfloat16 g_qh[(size_t)B_*N_*D_];
__device__ __nv_bfloat16 g_ql[(size_t)B_*N_*D_];
__device__ __nv_bfloat16 g_kh[(size_t)B_*S_*KVE];
__device__ __nv_bfloat16 g_kl[(size_t)B_*S_*KVE];
__device__ __nv_bfloat16 g_vh[(size_t)B_*S_*KVE];
__device__ __nv_bfloat16 g_vl[(size_t)B_*S_*KVE];
__device__ float  g_att[(size_t)B_*N_*D_];
__device__ float  g_rfx[B_*N_];
__device__ float  g_rfy[B_*S_];
__device__ float  g_rf2[B_*N_];
__device__ double g_part[4*256];
__device__ double g_wsum[4];

// ---------------- warp reductions -------------------------------------------
__device__ __forceinline__ void warp_sum2(float& a, float& b) {
    #pragma unroll
    for (int o = 16; o; o >>= 1) {
        a += __shfl_xor_sync(0xffffffffu, a, o);
        b += __shfl_xor_sync(0xffffffffu, b, o);
    }
}
__device__ __forceinline__ void warp_summax(float& s, float& m) {
    #pragma unroll
    for (int o = 16; o; o >>= 1) {
        s += __shfl_xor_sync(0xffffffffu, s, o);
        m = fmaxf(m, __shfl_xor_sync(0xffffffffu, m, o));
    }
}
__device__ __forceinline__ float block_sum(float v, float* sbuf) {
    #pragma unroll
    for (int o = 16; o; o >>= 1) v += __shfl_xor_sync(0xffffffffu, v, o);
    int w = threadIdx.x >> 5, l = threadIdx.x & 31;
    if (!l) sbuf[w] = v;
    __syncthreads();
    if (threadIdx.x < 8) {
        v = sbuf[threadIdx.x];
        #pragma unroll
        for (int o = 4; o; o >>= 1) v += __shfl_xor_sync(0x000000ffu, v, o);
        if (!threadIdx.x) sbuf[0] = v;
    }
    __syncthreads();
    v = sbuf[0];
    __syncthreads();
    return v;
}

// ---------------- weight prep (fused) ----------------------------------------
__global__ void __launch_bounds__(256) absmean_all_kernel(const float* __restrict__ w0,
    const float* __restrict__ w1, const float* __restrict__ w2, const float* __restrict__ w3) {
    __shared__ float sbuf[16];
    int slot = blockIdx.y;
    const float* w = slot == 0 ? w0 : slot == 1 ? w1 : slot == 2 ? w2 : w3;
    int n = (slot == 1 || slot == 2) ? KVE * D_ : D_ * D_;
    float s = 0.f;
    for (int i = blockIdx.x * 256 + threadIdx.x; i < n; i += 256 * 256)
        s += fabsf(w[i]);
    s = block_sum(s, sbuf);
    if (!threadIdx.x) g_part[slot * 256 + blockIdx.x] = (double)s;
}
__global__ void __launch_bounds__(256) reduce_kernel() {
    __shared__ double sd[256];
    int slot = blockIdx.x;
    sd[threadIdx.x] = g_part[slot * 256 + threadIdx.x];
    __syncthreads();
    for (int o = 128; o; o >>= 1) {
        if (threadIdx.x < o) sd[threadIdx.x] += sd[threadIdx.x + o];
        __syncthreads();
    }
    if (!threadIdx.x) g_wsum[slot] = sd[0];
}
__global__ void __launch_bounds__(256) wquant_all_kernel(const float* __restrict__ w0,
    const float* __restrict__ w1, const float* __restrict__ w2, const float* __restrict__ w3) {
    int slot = blockIdx.y;
    const float* w = slot == 0 ? w0 : slot == 1 ? w1 : slot == 2 ? w2 : w3;
    __nv_bfloat16* out = slot == 0 ? g_wqt : slot == 1 ? g_wkt : slot == 2 ? g_wvt : g_wot;
    int n = (slot == 1 || slot == 2) ? KVE * D_ : D_ * D_;
    double invcnt = 1.0 / (double)n;
    float mean  = (float)(g_wsum[slot] * invcnt);
    float scale = 1.0f / fmaxf(mean, 1e-5f);
    for (int i = blockIdx.x * 256 + threadIdx.x; i < n; i += gridDim.x * 256) {
        float t = fminf(fmaxf(rintf(w[i] * scale), -1.f), 1.f);
        out[i] = __float2bfloat16(t);
    }
}

// ---------------- activation quant: warp-per-row -----------------------------
__device__ __forceinline__ uint32_t q2(float a, float b, float r, float sc) {
    __nv_bfloat16 qa = __float2bfloat16(fminf(fmaxf(rintf((a*r)*sc), -128.f), 127.f));
    __nv_bfloat16 qb = __float2bfloat16(fminf(fmaxf(rintf((b*r)*sc), -128.f), 127.f));
    return ((uint32_t)__bfloat16_as_ushort(qb) << 16) | __bfloat16_as_ushort(qa);
}

__global__ void __launch_bounds__(256) act_quant_kernel(const float* __restrict__ X,
                                                        const float* __restrict__ Y) {
    int rid  = blockIdx.x * 8 + (threadIdx.x >> 5);
    int lane = threadIdx.x & 31;
    int which = rid >= B_ * N_;
    size_t row = which ? rid - B_ * N_ : rid;
    const float* src = (which ? Y : X) + row * D_;
    __nv_bfloat16* Q  = (which ? g_yq : g_xq) + row * D_;
    float*         RF = which ? g_rfy : g_rfx;

    float4 v[8];
    #pragma unroll
    for (int j = 0; j < 8; j++) v[j] = ((const float4*)src)[lane + j * 32];

    float ssq = 0.f, am = 0.f;
    #pragma unroll
    for (int j = 0; j < 8; j++) {
        ssq += v[j].x*v[j].x + v[j].y*v[j].y + v[j].z*v[j].z + v[j].w*v[j].w;
        am = fmaxf(am, fmaxf(fmaxf(fabsf(v[j].x), fabsf(v[j].y)),
                             fmaxf(fabsf(v[j].z), fabsf(v[j].w))));
    }
    warp_summax(ssq, am);
    float r = 1.0f / sqrtf(ssq * (1.0f/1024.0f) + 1e-6f);
    am *= r;
    float sc = 127.0f / fmaxf(am, 1e-5f);

    #pragma unroll
    for (int j = 0; j < 8; j++) {
        uint2 st;
        st.x = q2(v[j].x, v[j].y, r, sc);
        st.y = q2(v[j].z, v[j].w, r, sc);
        *(uint2*)(Q + (lane + j * 32) * 4) = st;
    }
    if (!lane) RF[row] = 1.0f / sc;
}

// ---------------- fused LayerNorm + rms_norm + act_quant (warp-per-row) ----
__global__ void __launch_bounds__(256) ln_quant_kernel(const float* __restrict__ gamma,
                                                       const float* __restrict__ beta) {
    int rid  = blockIdx.x * 8 + (threadIdx.x >> 5);
    int lane = threadIdx.x & 31;
    const float* src = g_att + (size_t)rid * D_;

    float4 v[8], gv[8], bv[8];
    #pragma unroll
    for (int j = 0; j < 8; j++) {
        v[j]  = ((const float4*)src)[lane + j * 32];
        gv[j] = ((const float4*)gamma)[lane + j * 32];
        bv[j] = ((const float4*)beta)[lane + j * 32];
    }

    float s = 0.f, sq = 0.f;
    #pragma unroll
    for (int j = 0; j < 8; j++) {
        s  += v[j].x + v[j].y + v[j].z + v[j].w;
        sq += v[j].x*v[j].x + v[j].y*v[j].y + v[j].z*v[j].z + v[j].w*v[j].w;
    }
    warp_sum2(s, sq);
    float mu  = s * (1.0f/1024.0f);
    float var = sq * (1.0f/1024.0f) - mu * mu;
    float rs  = 1.0f / sqrtf(var + 1e-5f);

    float m2 = 0.f, am = 0.f;
    #pragma unroll
    for (int j = 0; j < 8; j++) {
        v[j].x = ((v[j].x - mu) * rs) * gv[j].x + bv[j].x;
        v[j].y = ((v[j].y - mu) * rs) * gv[j].y + bv[j].y;
        v[j].z = ((v[j].z - mu) * rs) * gv[j].z + bv[j].z;
        v[j].w = ((v[j].w - mu) * rs) * gv[j].w + bv[j].w;
        m2 += v[j].x*v[j].x + v[j].y*v[j].y + v[j].z*v[j].z + v[j].w*v[j].w;
        am = fmaxf(am, fmaxf(fmaxf(fabsf(v[j].x), fabsf(v[j].y)),
                             fmaxf(fabsf(v[j].z), fabsf(v[j].w))));
    }
    warp_summax(m2, am);
    float r2 = 1.0f / sqrtf(m2 * (1.0f/1024.0f) + 1e-6f);
    am *= r2;
    float sc = 127.0f / fmaxf(am, 1e-5f);

    __nv_bfloat16* Q = g_a2q + (size_t)rid * D_;
    #pragma unroll
    for (int j = 0; j < 8; j++) {
        uint2 st;
        st.x = q2(v[j].x, v[j].y, r2, sc);
        st.y = q2(v[j].z, v[j].w, r2, sc);
        *(uint2*)(Q + (lane + j * 32) * 4) = st;
    }
    if (!lane) g_rf2[rid] = 1.0f / sc;
}

// ---------------- mma / ldmatrix / cp.async helpers -------------------------
__device__ __forceinline__ void ldsm4(uint32_t (&r)[4], uint32_t a) {
    asm volatile("ldmatrix.sync.aligned.m8n8.x4.shared.b16 {%0,%1,%2,%3}, [%4];"
                 : "=r"(r[0]), "=r"(r[1]), "=r"(r[2]), "=r"(r[3]) : "r"(a));
}
__device__ __forceinline__ void ldsm4t(uint32_t (&r)[4], uint32_t a) {
    asm volatile("ldmatrix.sync.aligned.m8n8.x4.trans.shared.b16 {%0,%1,%2,%3}, [%4];"
                 : "=r"(r[0]), "=r"(r[1]), "=r"(r[2]), "=r"(r[3]) : "r"(a));
}
__device__ __forceinline__ void mma_bf16(float (&d)[4], const uint32_t (&a)[4],
                                         uint32_t b0, uint32_t b1) {
    asm volatile("mma.sync.aligned.m16n8k16.row.col.f32.bf16.bf16.f32 "
                 "{%0,%1,%2,%3}, {%4,%5,%6,%7}, {%8,%9}, {%0,%1,%2,%3};"
                 : "+f"(d[0]), "+f"(d[1]), "+f"(d[2]), "+f"(d[3])
                 : "r"(a[0]), "r"(a[1]), "r"(a[2]), "r"(a[3]), "r"(b0), "r"(b1));
}
__device__ __forceinline__ void cpa16(uint32_t s, const void* g) {
    asm volatile("cp.async.cg.shared.global [%0], [%1], 16;" :: "r"(s), "l"(g));
}
#define CP_COMMIT asm volatile("cp.async.commit_group;")
#define CP_WAIT2  asm volatile("cp.async.wait_group 2;")
#define CP_WAIT0  asm volatile("cp.async.wait_group 0;")

__device__ __forceinline__ uint32_t pack_hl(float x, float y, uint32_t& lo) {
    __nv_bfloat16 hx = __float2bfloat16(x), hy = __float2bfloat16(y);
    __nv_bfloat16 lx = __float2bfloat16(x - __bfloat162float(hx));
    __nv_bfloat16 ly = __float2bfloat16(y - __bfloat162float(hy));
    lo = ((uint32_t)__bfloat16_as_ushort(ly) << 16) | __bfloat16_as_ushort(lx);
    return ((uint32_t)__bfloat16_as_ushort(hy) << 16) | __bfloat16_as_ushort(hx);
}

// ---------------- exact integer GEMM via bf16 MMA (4-stage cp.async) -------
#define G_SMEM4 (4 * 10240 * 2)
template<int MODE>   // 0: fp32 C; 1: hi/lo bf16 planes
__device__ __forceinline__ void gemm4(const __nv_bfloat16* __restrict__ A,
                                      const __nv_bfloat16* __restrict__ W,
                                      float* __restrict__ C,
                                      __nv_bfloat16* __restrict__ Ch,
                                      __nv_bfloat16* __restrict__ Cl,
                                      const float* __restrict__ rowf,
                                      int slot, double invcnt, float extra, int Nn,
                                      int m0, int n0) {
    extern __shared__ char smg[];
    __nv_bfloat16* sA = (__nv_bfloat16*)smg;
    __nv_bfloat16* sB = (__nv_bfloat16*)(smg + 4 * 10240);
    const int K = 1024, T = 32;
    int tid = threadIdx.x, lane = tid & 31, w = tid >> 5;
    int warpM = w & 1, warpN = w >> 1;
    int m0_ = m0, n0_ = n0;

    float acc[4][4][4];
    #pragma unroll
    for (int a = 0; a < 4; a++)
        #pragma unroll
        for (int b = 0; b < 4; b++)
            #pragma unroll
            for (int c = 0; c < 4; c++) acc[a][b][c] = 0.f;

    uint32_t sAb = (uint32_t)__cvta_generic_to_shared(sA);
    uint32_t sBb = (uint32_t)__cvta_generic_to_shared(sB);
    int aRow = warpM * 64 + (lane & 15);
    int aCol = (lane >> 4) << 3;
    int bRow = warpN * 32 + ((lane & 16) >> 1) + (lane & 7);
    int bCol = lane & 8;
    int ldr = tid >> 2, ldsg = (tid & 3) * 8;

    #define GLOAD(t, buf) do {                                                 \
        uint32_t bo = (uint32_t)(buf) * 10240u;                                \
        int k0 = (t) * 32;                                                     \
        _Pragma("unroll")                                                      \
        for (int i = 0; i < 2; i++) {                                          \
            int r = ldr + i * 64;                                              \
            cpa16(sAb + bo + (uint32_t)((r * 40 + ldsg) * 2),                  \
                  A + (size_t)(m0_ + r) * K + k0 + ldsg);                      \
            cpa16(sBb + bo + (uint32_t)((r * 40 + ldsg) * 2),                  \
                  W + (size_t)(n0_ + r) * K + k0 + ldsg);                      \
        }                                                                      \
    } while (0)

    GLOAD(0, 0); CP_COMMIT;
    GLOAD(1, 1); CP_COMMIT;
    GLOAD(2, 2); CP_COMMIT;

    #pragma unroll 1
    for (int t = 0; t < T; t++) {
        CP_WAIT2;
        __syncthreads();
        if (t + 3 < T) GLOAD(t + 3, (t + 3) & 3);
        CP_COMMIT;
        uint32_t bo = (uint32_t)(t & 3) * 10240u;
        #pragma unroll
        for (int ks = 0; ks < 32; ks += 16) {
            uint32_t af[4][4];
            #pragma unroll
            for (int mi = 0; mi < 4; mi++)
                ldsm4(af[mi], sAb + bo + (uint32_t)(((aRow + mi * 16) * 40 + ks + aCol) * 2));
            uint32_t bf[2][4];
            #pragma unroll
            for (int nb = 0; nb < 2; nb++)
                ldsm4(bf[nb], sBb + bo + (uint32_t)(((bRow + nb * 16) * 40 + ks + bCol) * 2));
            #pragma unroll
            for (int mi = 0; mi < 4; mi++)
                #pragma unroll
                for (int ni = 0; ni < 4; ni++)
                    mma_bf16(acc[mi][ni], af[mi],
                             bf[ni >> 1][(ni & 1) * 2], bf[ni >> 1][(ni & 1) * 2 + 1]);
        }
        // no trailing barrier — next iteration's top barrier (after CP_WAIT2)
        // orders MMA reads of buf t before GLOAD(t+4) overwrites it.
    }
    #undef GLOAD

    float wf = fmaxf((float)(g_wsum[slot] * invcnt), 1e-5f);
    float sgl = wf * extra;
    #pragma unroll
    for (int mi = 0; mi < 4; mi++) {
        int m = m0_ + warpM * 64 + mi * 16 + (lane >> 2);
        float f0 = rowf[m] * sgl, f1 = rowf[m + 8] * sgl;
        #pragma unroll
        for (int ni = 0; ni < 4; ni++) {
            int n = n0_ + warpN * 32 + ni * 8 + (lane & 3) * 2;
            if (MODE == 0) {
                *(float2*)(C + (size_t)m * Nn + n) =
                    make_float2(acc[mi][ni][0] * f0, acc[mi][ni][1] * f0);
                *(float2*)(C + (size_t)(m + 8) * Nn + n) =
                    make_float2(acc[mi][ni][2] * f1, acc[mi][ni][3] * f1);
            } else {
                uint32_t lo0, lo1;
                uint32_t hi0 = pack_hl(acc[mi][ni][0] * f0, acc[mi][ni][1] * f0, lo0);
                uint32_t hi1 = pack_hl(acc[mi][ni][2] * f1, acc[mi][ni][3] * f1, lo1);
                *(uint32_t*)(Ch + (size_t)m * Nn + n) = hi0;
                *(uint32_t*)(Cl + (size_t)m * Nn + n) = lo0;
                *(uint32_t*)(Ch + (size_t)(m + 8) * Nn + n) = hi1;
                *(uint32_t*)(Cl + (size_t)(m + 8) * Nn + n) = lo1;
            }
        }
    }
}

// merged q/k/v projection GEMM: blocks [0,1024) = q, [1024,1152) = k, [1152,1280) = v
__global__ void __launch_bounds__(256, 2) gemm_qkv_kernel() {
    int blk = blockIdx.x;
    if (blk < 1024) {
        gemm4<1>(g_xq, g_wqt, nullptr, g_qh, g_ql, g_rfx, 0, 1.0/(1024.0*1024.0),
                 0.125f, D_, (blk >> 3) * 128, (blk & 7) * 128);
    } else if (blk < 1152) {
        int t = blk - 1024;
        gemm4<1>(g_yq, g_wkt, nullptr, g_kh, g_kl, g_rfy, 1, 1.0/(512.0*1024.0),
                 1.0f, KVE, (t >> 2) * 128, (t & 3) * 128);
    } else {
        int t = blk - 1152;
        gemm4<1>(g_yq, g_wvt, nullptr, g_vh, g_vl, g_rfy, 2, 1.0/(512.0*1024.0),
                 1.0f, KVE, (t >> 2) * 128, (t & 3) * 128);
    }
}
__global__ void __launch_bounds__(256, 2) gemm_o_kernel(float* __restrict__ out) {
    gemm4<0>(g_a2q, g_wot, out, nullptr, nullptr, g_rf2, 3, 1.0/(1024.0*1024.0),
             1.0f, D_, (int)blockIdx.y * 128, (int)blockIdx.x * 128);
}

// ---------------- attention: hi/lo-split bf16 MMA ---------------------------
#define ATT_SMEM ((2 * 256 * 72 + 2 * 64 * 72) * 2)

__global__ void __launch_bounds__(128) attn_mma_kernel() {
    extern __shared__ __nv_bfloat16 sm[];
    __nv_bfloat16* sKVh = sm;
    __nv_bfloat16* sKVl = sm + 256 * 72;
    __nv_bfloat16* sQh  = sm + 2 * 256 * 72;
    __nv_bfloat16* sQl  = sQh + 64 * 72;

    int tid = threadIdx.x, lane = tid & 31, w = tid >> 5;
    int blk = blockIdx.x;
    int qt = blk & 15, qh = (blk >> 4) & 15, b = blk >> 8;
    int h = qh >> 1;

    uint32_t sQhB  = (uint32_t)__cvta_generic_to_shared(sQh);
    uint32_t sQlB  = (uint32_t)__cvta_generic_to_shared(sQl);
    uint32_t sKVhB = (uint32_t)__cvta_generic_to_shared(sKVh);
    uint32_t sKVlB = (uint32_t)__cvta_generic_to_shared(sKVl);

    const __nv_bfloat16* Qh = g_qh + ((size_t)(b * N_ + qt * 64)) * D_ + qh * HD;
    const __nv_bfloat16* Ql = g_ql + ((size_t)(b * N_ + qt * 64)) * D_ + qh * HD;
    const __nv_bfloat16* Kh = g_kh + (size_t)b * S_ * KVE + h * HD;
    const __nv_bfloat16* Kl = g_kl + (size_t)b * S_ * KVE + h * HD;
    const __nv_bfloat16* Vh = g_vh + (size_t)b * S_ * KVE + h * HD;
    const __nv_bfloat16* Vl = g_vl + (size_t)b * S_ * KVE + h * HD;

    #pragma unroll
    for (int i = tid; i < 512; i += 128) {
        int r = i >> 3, c = (i & 7) * 16;
        cpa16(sQhB + (uint32_t)(r * 144 + c), Qh + (size_t)r * D_ + c / 2);
        cpa16(sQlB + (uint32_t)(r * 144 + c), Ql + (size_t)r * D_ + c / 2);
    }
    #pragma unroll
    for (int i = tid; i < 2048; i += 128) {
        int r = i >> 3, c = (i & 7) * 16;
        cpa16(sKVhB + (uint32_t)(r * 144 + c), Kh + (size_t)r * KVE + c / 2);
        cpa16(sKVlB + (uint32_t)(r * 144 + c), Kl + (size_t)r * KVE + c / 2);
    }
    CP_COMMIT;
    CP_WAIT0;
    __syncthreads();

    int arow = w * 16 + (lane & 15);
    int acb  = (lane & 16) >> 1;
    uint32_t qhf[4][4], qlf[4][4];
    #pragma unroll
    for (int kt = 0; kt < 4; kt++) {
        uint32_t off = (uint32_t)((arow * 72 + kt * 16 + acb) * 2);
        ldsm4(qhf[kt], sQhB + off);
        ldsm4(qlf[kt], sQlB + off);
    }

    float c[32][4];
    #pragma unroll
    for (int i = 0; i < 32; i++)
        #pragma unroll
        for (int j = 0; j < 4; j++) c[i][j] = 0.f;

    int brow = (lane & 7) + ((lane & 16) >> 1);
    int bcol = lane & 8;
    #pragma unroll
    for (int np = 0; np < 16; np++) {
        #pragma unroll
        for (int kt = 0; kt < 4; kt++) {
            uint32_t off = (uint32_t)(((np * 16 + brow) * 72 + kt * 16 + bcol) * 2);
            uint32_t bh[4], bl[4];
            ldsm4(bh, sKVhB + off);
            ldsm4(bl, sKVlB + off);
            mma_bf16(c[2*np  ], qhf[kt], bh[0], bh[1]);
            mma_bf16(c[2*np  ], qhf[kt], bl[0], bl[1]);
            mma_bf16(c[2*np  ], qlf[kt], bh[0], bh[1]);
            mma_bf16(c[2*np+1], qhf[kt], bh[2], bh[3]);
            mma_bf16(c[2*np+1], qhf[kt], bl[2], bl[3]);
            mma_bf16(c[2*np+1], qlf[kt], bh[2], bh[3]);
        }
    }
    __syncthreads();

    #pragma unroll
    for (int i = tid; i < 2048; i += 128) {
        int r = i >> 3, cc = (i & 7) * 16;
        cpa16(sKVhB + (uint32_t)(r * 144 + cc), Vh + (size_t)r * KVE + cc / 2);
        cpa16(sKVlB + (uint32_t)(r * 144 + cc), Vl + (size_t)r * KVE + cc / 2);
    }
    CP_COMMIT;

    float mx0 = -1e30f, mx1 = -1e30f;
    #pragma unroll
    for (int nt = 0; nt < 32; nt++) {
        mx0 = fmaxf(mx0, fmaxf(c[nt][0], c[nt][1]));
        mx1 = fmaxf(mx1, fmaxf(c[nt][2], c[nt][3]));
    }
    mx0 = fmaxf(mx0, __shfl_xor_sync(0xffffffffu, mx0, 1));
    mx0 = fmaxf(mx0, __shfl_xor_sync(0xffffffffu, mx0, 2));
    mx1 = fmaxf(mx1, __shfl_xor_sync(0xffffffffu, mx1, 1));
    mx1 = fmaxf(mx1, __shfl_xor_sync(0xffffffffu, mx1, 2));
    float s0 = 0.f, s1 = 0.f;
    #pragma unroll
    for (int nt = 0; nt < 32; nt++) {
        c[nt][0] = __expf(c[nt][0] - mx0); s0 += c[nt][0];
        c[nt][1] = __expf(c[nt][1] - mx0); s0 += c[nt][1];
        c[nt][2] = __expf(c[nt][2] - mx1); s1 += c[nt][2];
        c[nt][3] = __expf(c[nt][3] - mx1); s1 += c[nt][3];
    }
    s0 += __shfl_xor_sync(0xffffffffu, s0, 1);
    s0 += __shfl_xor_sync(0xffffffffu, s0, 2);
    s1 += __shfl_xor_sync(0xffffffffu, s1, 1);
    s1 += __shfl_xor_sync(0xffffffffu, s1, 2);
    float i0 = 1.0f / s0, i1 = 1.0f / s1;
    #pragma unroll
    for (int nt = 0; nt < 32; nt++) {
        c[nt][0] *= i0; c[nt][1] *= i0; c[nt][2] *= i1; c[nt][3] *= i1;
    }
    CP_WAIT0;
    __syncthreads();

    float o[8][4];
    #pragma unroll
    for (int i = 0; i < 8; i++)
        #pragma unroll
        for (int j = 0; j < 4; j++) o[i][j] = 0.f;

    int vrow = (lane & 7) + (lane & 8);
    int vcb  = (lane & 16) >> 1;
    #pragma unroll
    for (int kt = 0; kt < 16; kt++) {
        uint32_t phi[4], plo[4];
        phi[0] = pack_hl(c[2*kt  ][0], c[2*kt  ][1], plo[0]);
        phi[1] = pack_hl(c[2*kt  ][2], c[2*kt  ][3], plo[1]);
        phi[2] = pack_hl(c[2*kt+1][0], c[2*kt+1][1], plo[2]);
        phi[3] = pack_hl(c[2*kt+1][2], c[2*kt+1][3], plo[3]);
        #pragma unroll
        for (int dp = 0; dp < 4; dp++) {
            uint32_t off = (uint32_t)(((kt * 16 + vrow) * 72 + dp * 16 + vcb) * 2);
            uint32_t bh[4], bl[4];
            ldsm4t(bh, sKVhB + off);
            ldsm4t(bl, sKVlB + off);
            mma_bf16(o[2*dp  ], phi, bh[0], bh[1]);
            mma_bf16(o[2*dp  ], phi, bl[0], bl[1]);
            mma_bf16(o[2*dp  ], plo, bh[0], bh[1]);
            mma_bf16(o[2*dp+1], phi, bh[2], bh[3]);
            mma_bf16(o[2*dp+1], phi, bl[2], bl[3]);
            mma_bf16(o[2*dp+1], plo, bh[2], bh[3]);
        }
    }

    float* Ob = g_att + ((size_t)(b * N_ + qt * 64 + w * 16 + (lane >> 2))) * D_ + qh * HD;
    #pragma unroll
    for (int nt = 0; nt < 8; nt++) {
        int col = nt * 8 + (lane & 3) * 2;
        *(float2*)(Ob + col)          = make_float2(o[nt][0], o[nt][1]);
        *(float2*)(Ob + 8 * D_ + col) = make_float2(o[nt][2], o[nt][3]);
    }
}

// ---------------- launch ----------------------------------------------------
extern "C" void kernel_launch(void* const* d_in, const int* in_sizes, int n_in,
                              void* d_out, int out_size) {
    const float* x  = (const float*)d_in[0];
    const float* y  = (const float*)d_in[1];
    const float* wq = (const float*)d_in[2];
    const float* wk = (const float*)d_in[3];
    const float* wv = (const float*)d_in[4];
    const float* wo = (const float*)d_in[5];
    const float* gamma = (const float*)d_in[6];
    const float* beta  = (const float*)d_in[7];
    float* out = (float*)d_out;

    cudaFuncSetAttribute(attn_mma_kernel,
                         cudaFuncAttributeMaxDynamicSharedMemorySize, ATT_SMEM);
    cudaFuncSetAttribute(gemm_qkv_kernel, cudaFuncAttributeMaxDynamicSharedMemorySize, G_SMEM4);
    cudaFuncSetAttribute(gemm_o_kernel,   cudaFuncAttributeMaxDynamicSharedMemorySize, G_SMEM4);

    absmean_all_kernel<<<dim3(256, 4), 256>>>(wq, wk, wv, wo);
    reduce_kernel<<<4, 256>>>();
    wquant_all_kernel<<<dim3(512, 4), 256>>>(wq, wk, wv, wo);

    act_quant_kernel<<<(B_ * N_ + B_ * S_) / 8, 256>>>(x, y);

    gemm_qkv_kernel<<<1280, 256, G_SMEM4>>>();

    attn_mma_kernel<<<B_ * HQ * (N_ / 64), 128, ATT_SMEM>>>();

    ln_quant_kernel<<<B_ * N_ / 8, 256>>>(gamma, beta);
    gemm_o_kernel<<<dim3(8, 128), 256, G_SMEM4>>>(out);
}